// round 8
// baseline (speedup 1.0000x reference)
#include <cuda_runtime.h>
#include <cstdint>
#include <cstddef>

// Problem dims (fixed)
#define BB   32
#define TT   4096
#define DIN  256
#define HH   256
#define G4   1024   // 4*H

// ---------------- scratch (static device arrays; no allocation) ----------------
__device__ float g_xg[(size_t)BB * TT * G4];   // 512 MB : x @ Wx + b
__device__ float g_hseq[(size_t)BB * TT * HH]; // 128 MB : h_t for all t
// tagged exchange: [slot][group][hidx][batch] = {h, tag} in one 8B word,
// accessed ONLY with relaxed atomics (spec-guaranteed single-copy atomic).
__device__ unsigned long long g_hx[2][16][256][2];

__global__ void init_kernel() {   // zero tags for graph replays
    const int i = blockIdx.x * 256 + threadIdx.x;   // 16384 u64s
    ((unsigned long long*)g_hx)[i] = 0ull;
}

// ---------------- PTX helpers ----------------
__device__ __forceinline__ unsigned long long ffma2(unsigned long long a,
                                                    unsigned long long b,
                                                    unsigned long long c) {
    unsigned long long d;
    asm("fma.rn.f32x2 %0, %1, %2, %3;" : "=l"(d) : "l"(a), "l"(b), "l"(c));
    return d;
}
__device__ __forceinline__ unsigned long long addx2(unsigned long long a,
                                                    unsigned long long b) {
    unsigned long long d;
    asm("add.rn.f32x2 %0, %1, %2;" : "=l"(d) : "l"(a), "l"(b));
    return d;
}
__device__ __forceinline__ unsigned long long pk2(float lo, float hi) {
    unsigned long long r;
    asm("mov.b64 %0, {%1,%2};" : "=l"(r) : "f"(lo), "f"(hi));
    return r;
}
__device__ __forceinline__ float2 unpk2(unsigned long long v) {
    float lo, hi;
    asm("mov.b64 {%0,%1}, %2;" : "=f"(lo), "=f"(hi) : "l"(v));
    return make_float2(lo, hi);
}
// relaxed 8B atomics: tear-free by the PTX memory model, no fence cost
__device__ __forceinline__ void st_rlx64(unsigned long long* p, unsigned long long v) {
    asm volatile("st.relaxed.gpu.global.u64 [%0], %1;" :: "l"(p), "l"(v) : "memory");
}
__device__ __forceinline__ unsigned long long ld_rlx64(const unsigned long long* p) {
    unsigned long long v;
    asm volatile("ld.relaxed.gpu.global.u64 %0, [%1];" : "=l"(v) : "l"(p) : "memory");
    return v;
}

// ---------------- fp32 GEMM (f32x2 inner loop): C = A@B + bias ----------------
__global__ void __launch_bounds__(256) sgemm_bias_128(
    const float* __restrict__ A, const float* __restrict__ B,
    const float* __restrict__ bias, float* __restrict__ C,
    int M, int N, int K)
{
    __shared__ __align__(16) float As[8][128];
    __shared__ __align__(16) float Bs[8][128];

    const int tid = threadIdx.x;
    const int bm  = blockIdx.y;
    const int bn  = blockIdx.x;
    const int tx  = tid & 15;
    const int ty  = tid >> 4;

    const int arow = tid >> 1;
    const int ak   = (tid & 1) * 4;
    const int brow = tid >> 5;
    const int bcol = (tid & 31) * 4;

    const float* Aptr = A + (size_t)(bm * 128 + arow) * K + ak;
    const float* Bptr = B + (size_t)brow * N + bn * 128 + bcol;

    unsigned long long acc2[8][4];
#pragma unroll
    for (int i = 0; i < 8; i++)
#pragma unroll
        for (int jp = 0; jp < 4; jp++) acc2[i][jp] = 0ull;

    for (int k0 = 0; k0 < K; k0 += 8) {
        const float4 va = *(const float4*)(Aptr + k0);
        const float4 vb = *(const float4*)(Bptr + (size_t)k0 * N);
        __syncthreads();
        As[ak + 0][arow] = va.x;
        As[ak + 1][arow] = va.y;
        As[ak + 2][arow] = va.z;
        As[ak + 3][arow] = va.w;
        *(float4*)&Bs[brow][bcol] = vb;
        __syncthreads();

#pragma unroll
        for (int k = 0; k < 8; k++) {
            float a0[4], a1[4];
            *(float4*)a0 = *(const float4*)&As[k][ty * 4];
            *(float4*)a1 = *(const float4*)&As[k][64 + ty * 4];
            const ulonglong2 bp0 = *(const ulonglong2*)&Bs[k][tx * 4];
            const ulonglong2 bp1 = *(const ulonglong2*)&Bs[k][64 + tx * 4];
#pragma unroll
            for (int i = 0; i < 4; i++) {
                const unsigned long long ad0 = pk2(a0[i], a0[i]);
                acc2[i][0] = ffma2(ad0, bp0.x, acc2[i][0]);
                acc2[i][1] = ffma2(ad0, bp0.y, acc2[i][1]);
                acc2[i][2] = ffma2(ad0, bp1.x, acc2[i][2]);
                acc2[i][3] = ffma2(ad0, bp1.y, acc2[i][3]);
                const unsigned long long ad1 = pk2(a1[i], a1[i]);
                acc2[i + 4][0] = ffma2(ad1, bp0.x, acc2[i + 4][0]);
                acc2[i + 4][1] = ffma2(ad1, bp0.y, acc2[i + 4][1]);
                acc2[i + 4][2] = ffma2(ad1, bp1.x, acc2[i + 4][2]);
                acc2[i + 4][3] = ffma2(ad1, bp1.y, acc2[i + 4][3]);
            }
        }
    }

    const float* bptr = bias + bn * 128;
    const ulonglong2 bv0 = *(const ulonglong2*)&bptr[tx * 4];
    const ulonglong2 bv1 = *(const ulonglong2*)&bptr[64 + tx * 4];

#pragma unroll
    for (int i = 0; i < 8; i++) {
        const int row = bm * 128 + ((i < 4) ? (ty * 4 + i) : (64 + ty * 4 + (i - 4)));
        ulonglong2 o0, o1;
        o0.x = addx2(acc2[i][0], bv0.x);
        o0.y = addx2(acc2[i][1], bv0.y);
        o1.x = addx2(acc2[i][2], bv1.x);
        o1.y = addx2(acc2[i][3], bv1.y);
        *(ulonglong2*)&C[(size_t)row * N + bn * 128 + tx * 4]      = o0;
        *(ulonglong2*)&C[(size_t)row * N + bn * 128 + 64 + tx * 4] = o1;
    }
}

// ---------------- recurrence: warp-local gates + relaxed-atomic exchange -------
// 128 CTAs = 16 groups (batch pairs) x 8 ranks. Rank j owns 128 gate-columns.
// NEW column mapping: within a warp, lane = kh*16 + gate*4 + hr, so after the
// K-half reduce (shfl_xor 16) each warp holds ALL 4 gates for 4 h-indices
// (hh = w*4 + hr). Gate gather = 8 shfl.idx; activation runs in lanes 0-7
// (lane<4 -> batch0, 4-7 -> batch1) with c-state in those lanes' registers.
// gsm/csm and 2 of 3 per-step barriers are GONE; the single remaining barrier
// protects the parity-double-buffered hs[2][2][256].
// Exchange unchanged from R7: {h, tag} in one 8B word via relaxed atomics;
// every thread polls its own two words until both tags >= t+1.
__global__ void __launch_bounds__(256, 1) lstm_rec(const float* __restrict__ Wh)
{
    const int cta  = blockIdx.x;
    const int grp  = cta >> 3;
    const int j    = cta & 7;
    const int b0   = grp * 2, b1 = b0 + 1;
    const int tid  = threadIdx.x;
    const int w    = tid >> 5;
    const int lane = tid & 31;
    const int kh   = lane >> 4;              // K-half
    const int r16  = lane & 15;
    const int gate = r16 >> 2;               // 0..3 (i,f,g,o)
    const int hr   = r16 & 3;                // h-index within warp's 4
    const int hh   = w * 4 + hr;             // h-index within CTA's 32
    const int colg = gate * 256 + j * 32 + hh;   // column in [0,1024)

    __shared__ __align__(16) float hs[2][2][256];   // parity x batch x h

    // persistent packed weights: w2[jj] = (Wh[k0+2jj][colg], Wh[k0+2jj+1][colg])
    unsigned long long w2[64];
    {
        const float* wp = Wh + (size_t)(kh * 128) * G4 + colg;
#pragma unroll
        for (int jj = 0; jj < 64; jj++) {
            const float lo = __ldg(&wp[(size_t)(2 * jj) * G4]);
            const float hi = __ldg(&wp[(size_t)(2 * jj + 1) * G4]);
            w2[jj] = pk2(lo, hi);
        }
    }

    hs[0][0][tid] = 0.f;
    hs[0][1][tid] = 0.f;
    hs[1][0][tid] = 0.f;
    hs[1][1][tid] = 0.f;
    float creg = 0.f;   // c-state lives in lanes 0-7 of each warp
    __syncthreads();

    // preload xg for t=0 (lanes 0-15 hold the gate columns)
    float xv0 = 0.f, xv1 = 0.f;
    if (kh == 0) {
        xv0 = __ldg(&g_xg[((size_t)(b0 * TT)) * G4 + colg]);
        xv1 = __ldg(&g_xg[((size_t)(b1 * TT)) * G4 + colg]);
    }

    const int sb = lane & 3;   // shfl source base (= hr for lanes 0-7)

    for (int t = 0; t < TT; t++) {
        const int p = t & 1;

        // partial dot over this lane's K-half, 2 batches, f32x2 packed along K
        const ulonglong2* h0v = (const ulonglong2*)&hs[p][0][kh * 128];
        const ulonglong2* h1v = (const ulonglong2*)&hs[p][1][kh * 128];
        unsigned long long a00 = 0ull, a01 = 0ull, a10 = 0ull, a11 = 0ull;
#pragma unroll
        for (int jj = 0; jj < 32; jj++) {
            const ulonglong2 h0 = h0v[jj];
            const ulonglong2 h1 = h1v[jj];
            a00 = ffma2(w2[2 * jj],     h0.x, a00);
            a01 = ffma2(w2[2 * jj + 1], h0.y, a01);
            a10 = ffma2(w2[2 * jj],     h1.x, a10);
            a11 = ffma2(w2[2 * jj + 1], h1.y, a11);
        }
        float s0, s1;
        {
            const float2 u0 = unpk2(a00), u1 = unpk2(a01);
            const float2 v0 = unpk2(a10), v1 = unpk2(a11);
            s0 = (u0.x + u0.y) + (u1.x + u1.y);
            s1 = (v0.x + v0.y) + (v1.x + v1.y);
        }
        // cross-K-half reduce; lanes 0-15 now hold full column sums
        s0 += __shfl_xor_sync(0xffffffffu, s0, 16);
        s1 += __shfl_xor_sync(0xffffffffu, s1, 16);
        const float g0 = s0 + xv0;   // bias folded into xg (valid lanes 0-15)
        const float g1 = s1 + xv1;

        // warp-local gate gather: gates for h-index sb live at lanes sb,+4,+8,+12
        const float i0 = __shfl_sync(0xffffffffu, g0, sb);
        const float f0 = __shfl_sync(0xffffffffu, g0, sb + 4);
        const float z0 = __shfl_sync(0xffffffffu, g0, sb + 8);
        const float o0 = __shfl_sync(0xffffffffu, g0, sb + 12);
        const float i1 = __shfl_sync(0xffffffffu, g1, sb);
        const float f1 = __shfl_sync(0xffffffffu, g1, sb + 4);
        const float z1 = __shfl_sync(0xffffffffu, g1, sb + 8);
        const float o1 = __shfl_sync(0xffffffffu, g1, sb + 12);

        const int   s    = (t + 1) & 1;
        const float tagf = (float)(t + 1);

        // activation in lanes 0-7: lane<4 -> batch0 h=w*4+sb, 4-7 -> batch1
        if (lane < 8) {
            const int  bb = lane >> 2;
            const float gi = bb ? i1 : i0;
            const float gf = bb ? f1 : f0;
            const float gz = bb ? z1 : z0;
            const float go = bb ? o1 : o0;
            const float si = 1.f / (1.f + __expf(-gi));
            const float sf = 1.f / (1.f + __expf(-gf));
            const float so = 1.f / (1.f + __expf(-go));
            const float tg = 2.f / (1.f + __expf(-2.f * gz)) - 1.f;
            creg = sf * creg + si * tg;
            const float tc = 2.f / (1.f + __expf(-2.f * creg)) - 1.f;
            const float hn = so * tc;
            const int hidx = j * 32 + w * 4 + sb;
            if (t + 1 < TT)
                st_rlx64(&g_hx[s][grp][hidx][bb], pk2(hn, tagf));
            const int bg = bb ? b1 : b0;
            g_hseq[((size_t)(bg * TT + t)) * HH + hidx] = hn;
        }

        if (t + 1 < TT) {
            // prefetch next xg (in flight during the poll)
            if (kh == 0) {
                xv0 = __ldg(&g_xg[((size_t)(b0 * TT + (t + 1))) * G4 + colg]);
                xv1 = __ldg(&g_xg[((size_t)(b1 * TT + (t + 1))) * G4 + colg]);
            }
            // each thread polls its OWN two tagged words; hit == data
            const unsigned long long* src = &g_hx[s][grp][tid][0];
            float2 d0, d1;
            for (;;) {
                const unsigned long long v0 = ld_rlx64(src);
                const unsigned long long v1 = ld_rlx64(src + 1);
                d0 = unpk2(v0);
                d1 = unpk2(v1);
                if (d0.y >= tagf && d1.y >= tagf) break;
            }
            hs[s][0][tid] = d0.x;   // write buffer = parity s = p^1
            hs[s][1][tid] = d1.x;
            __syncthreads();        // single barrier per step
        }
    }
}

// ---------------- launch ----------------
extern "C" void kernel_launch(void* const* d_in, const int* in_sizes, int n_in,
                              void* d_out, int out_size)
{
    const float* x  = (const float*)d_in[0];   // [B,T,DIN]
    const float* Wx = (const float*)d_in[1];   // [DIN,4H]
    const float* Wh = (const float*)d_in[2];   // [H,4H]
    const float* b  = (const float*)d_in[3];   // [4H]
    const float* Wo = (const float*)d_in[4];   // [H,DOUT]
    const float* bo = (const float*)d_in[5];   // [DOUT]
    float* out = (float*)d_out;                // [B,T,DOUT]

    float *xg_ptr = nullptr, *hseq_ptr = nullptr;
    cudaGetSymbolAddress((void**)&xg_ptr, g_xg);
    cudaGetSymbolAddress((void**)&hseq_ptr, g_hseq);

    // reset exchange tags (graph replays reuse device state)
    init_kernel<<<64, 256>>>();

    // 1) xg = x @ Wx + b : [131072,256] @ [256,1024]
    {
        dim3 grid(G4 / 128, (BB * TT) / 128);   // (8, 1024)
        sgemm_bias_128<<<grid, 256>>>(x, Wx, b, xg_ptr, BB * TT, G4, DIN);
    }

    // 2) recurrence over 4096 steps (16 groups x 8 CTAs, all co-resident)
    lstm_rec<<<128, 256>>>(Wh);

    // 3) out = hseq @ Wo + bo : [131072,256] @ [256,256]
    {
        dim3 grid(256 / 128, (BB * TT) / 128);  // (2, 1024)
        sgemm_bias_128<<<grid, 256>>>(hseq_ptr, Wo, bo, out, BB * TT, 256, HH);
    }
}

// round 10
// speedup vs baseline: 1.2019x; 1.2019x over previous
#include <cuda_runtime.h>
#include <cstdint>
#include <cstddef>

// Problem dims (fixed)
#define BB   32
#define TT   4096
#define DIN  256
#define HH   256
#define G4   1024   // 4*H

// ---------------- scratch (static device arrays; no allocation) ----------------
__device__ float g_xg[(size_t)BB * TT * G4];   // 512 MB : x @ Wx + b
__device__ float g_hseq[(size_t)BB * TT * HH]; // 128 MB : h_t for all t
// tagged exchange: [slot][group][hidx][batch] = {h, tag} in one 8B word,
// accessed ONLY with relaxed atomics (spec-guaranteed single-copy atomic).
__device__ unsigned long long g_hx[2][16][256][2];

__global__ void init_kernel() {   // zero tags for graph replays
    const int i = blockIdx.x * 256 + threadIdx.x;   // 16384 u64s
    ((unsigned long long*)g_hx)[i] = 0ull;
}

// ---------------- PTX helpers ----------------
__device__ __forceinline__ unsigned long long ffma2(unsigned long long a,
                                                    unsigned long long b,
                                                    unsigned long long c) {
    unsigned long long d;
    asm("fma.rn.f32x2 %0, %1, %2, %3;" : "=l"(d) : "l"(a), "l"(b), "l"(c));
    return d;
}
__device__ __forceinline__ unsigned long long addx2(unsigned long long a,
                                                    unsigned long long b) {
    unsigned long long d;
    asm("add.rn.f32x2 %0, %1, %2;" : "=l"(d) : "l"(a), "l"(b));
    return d;
}
__device__ __forceinline__ unsigned long long pk2(float lo, float hi) {
    unsigned long long r;
    asm("mov.b64 %0, {%1,%2};" : "=l"(r) : "f"(lo), "f"(hi));
    return r;
}
__device__ __forceinline__ float2 unpk2(unsigned long long v) {
    float lo, hi;
    asm("mov.b64 {%0,%1}, %2;" : "=f"(lo), "=f"(hi) : "l"(v));
    return make_float2(lo, hi);
}
// relaxed 8B atomics: tear-free by the PTX memory model, no fence cost
__device__ __forceinline__ void st_rlx64(unsigned long long* p, unsigned long long v) {
    asm volatile("st.relaxed.gpu.global.u64 [%0], %1;" :: "l"(p), "l"(v) : "memory");
}
__device__ __forceinline__ unsigned long long ld_rlx64(const unsigned long long* p) {
    unsigned long long v;
    asm volatile("ld.relaxed.gpu.global.u64 %0, [%1];" : "=l"(v) : "l"(p) : "memory");
    return v;
}

// ---------------- fp32 GEMM (f32x2 inner loop): C = A@B + bias ----------------
__global__ void __launch_bounds__(256) sgemm_bias_128(
    const float* __restrict__ A, const float* __restrict__ B,
    const float* __restrict__ bias, float* __restrict__ C,
    int M, int N, int K)
{
    __shared__ __align__(16) float As[8][128];
    __shared__ __align__(16) float Bs[8][128];

    const int tid = threadIdx.x;
    const int bm  = blockIdx.y;
    const int bn  = blockIdx.x;
    const int tx  = tid & 15;
    const int ty  = tid >> 4;

    const int arow = tid >> 1;
    const int ak   = (tid & 1) * 4;
    const int brow = tid >> 5;
    const int bcol = (tid & 31) * 4;

    const float* Aptr = A + (size_t)(bm * 128 + arow) * K + ak;
    const float* Bptr = B + (size_t)brow * N + bn * 128 + bcol;

    unsigned long long acc2[8][4];
#pragma unroll
    for (int i = 0; i < 8; i++)
#pragma unroll
        for (int jp = 0; jp < 4; jp++) acc2[i][jp] = 0ull;

    for (int k0 = 0; k0 < K; k0 += 8) {
        const float4 va = *(const float4*)(Aptr + k0);
        const float4 vb = *(const float4*)(Bptr + (size_t)k0 * N);
        __syncthreads();
        As[ak + 0][arow] = va.x;
        As[ak + 1][arow] = va.y;
        As[ak + 2][arow] = va.z;
        As[ak + 3][arow] = va.w;
        *(float4*)&Bs[brow][bcol] = vb;
        __syncthreads();

#pragma unroll
        for (int k = 0; k < 8; k++) {
            float a0[4], a1[4];
            *(float4*)a0 = *(const float4*)&As[k][ty * 4];
            *(float4*)a1 = *(const float4*)&As[k][64 + ty * 4];
            const ulonglong2 bp0 = *(const ulonglong2*)&Bs[k][tx * 4];
            const ulonglong2 bp1 = *(const ulonglong2*)&Bs[k][64 + tx * 4];
#pragma unroll
            for (int i = 0; i < 4; i++) {
                const unsigned long long ad0 = pk2(a0[i], a0[i]);
                acc2[i][0] = ffma2(ad0, bp0.x, acc2[i][0]);
                acc2[i][1] = ffma2(ad0, bp0.y, acc2[i][1]);
                acc2[i][2] = ffma2(ad0, bp1.x, acc2[i][2]);
                acc2[i][3] = ffma2(ad0, bp1.y, acc2[i][3]);
                const unsigned long long ad1 = pk2(a1[i], a1[i]);
                acc2[i + 4][0] = ffma2(ad1, bp0.x, acc2[i + 4][0]);
                acc2[i + 4][1] = ffma2(ad1, bp0.y, acc2[i + 4][1]);
                acc2[i + 4][2] = ffma2(ad1, bp1.x, acc2[i + 4][2]);
                acc2[i + 4][3] = ffma2(ad1, bp1.y, acc2[i + 4][3]);
            }
        }
    }

    const float* bptr = bias + bn * 128;
    const ulonglong2 bv0 = *(const ulonglong2*)&bptr[tx * 4];
    const ulonglong2 bv1 = *(const ulonglong2*)&bptr[64 + tx * 4];

#pragma unroll
    for (int i = 0; i < 8; i++) {
        const int row = bm * 128 + ((i < 4) ? (ty * 4 + i) : (64 + ty * 4 + (i - 4)));
        ulonglong2 o0, o1;
        o0.x = addx2(acc2[i][0], bv0.x);
        o0.y = addx2(acc2[i][1], bv0.y);
        o1.x = addx2(acc2[i][2], bv1.x);
        o1.y = addx2(acc2[i][3], bv1.y);
        *(ulonglong2*)&C[(size_t)row * N + bn * 128 + tx * 4]      = o0;
        *(ulonglong2*)&C[(size_t)row * N + bn * 128 + 64 + tx * 4] = o1;
    }
}

// ---------------- recurrence: outer-product form + relaxed-atomic exchange -----
// 128 CTAs = 16 groups (batch pairs) x 8 ranks. Rank j owns 128 gate-columns
// colg(col) = (col>>5)*256 + j*32 + (col&31), col in [0,128).
// OUTER-PRODUCT decomposition: warp w owns K-slice [32w, 32w+32). Each lane
// loads ONE h per batch (hs[b][32w+lane] -- coalesced, 2 LDS wavefronts/warp
// instead of 128 broadcast wavefronts) and redistributes via shfl.idx inside
// the loop. Lane accumulates cols [4*lane, 4*lane+4) as 2 f32x2 pairs x 2
// batches; weights w2[32][2] (128 regs) persistent.
// Cross-warp K-reduce: coalesced STS to red[8][2][128], barrier, 256-thread
// add (+xg) -> gsm[256], barrier, R4-style 64-thread activation (csm SMEM).
// Exchange byte-identical to R7: {h, tag} 8B relaxed atomics; every thread
// polls its own two words until both tags >= t+1; 3 barriers/step.
__global__ void __launch_bounds__(256, 1) lstm_rec(const float* __restrict__ Wh)
{
    const int cta  = blockIdx.x;
    const int grp  = cta >> 3;
    const int j    = cta & 7;
    const int b0   = grp * 2, b1 = b0 + 1;
    const int tid  = threadIdx.x;
    const int w    = tid >> 5;
    const int lane = tid & 31;

    // reduce/act mapping: thread t -> (batch rb, column rcol)
    const int rb    = tid >> 7;            // 0/1
    const int rcol  = tid & 127;           // 0..127
    const int rcolg = (rcol >> 5) * 256 + j * 32 + (rcol & 31);

    __shared__ __align__(16) float hs[2][256];        // batch x h (single buffer)
    __shared__ __align__(16) float red[8][2][128];    // warp x batch x col
    __shared__ float gsm[256];                        // batch*128 + col
    __shared__ float csm[2][32];

    // persistent packed weights: w2[k][p] = (Wh[32w+k][colg(4*lane+2p)],
    //                                        Wh[32w+k][colg(4*lane+2p)+1])
    unsigned long long w2[32][2];
    {
        const int c0 = 4 * lane;           // col pairs (c0,c0+1) and (c0+2,c0+3)
        const int cg0 = (c0 >> 5) * 256 + j * 32 + (c0 & 31);       // pair 0
        const int c2 = c0 + 2;
        const int cg2 = (c2 >> 5) * 256 + j * 32 + (c2 & 31);       // pair 1
#pragma unroll
        for (int k = 0; k < 32; k++) {
            const float* wr = Wh + (size_t)(w * 32 + k) * G4;
            w2[k][0] = pk2(__ldg(&wr[cg0]), __ldg(&wr[cg0 + 1]));
            w2[k][1] = pk2(__ldg(&wr[cg2]), __ldg(&wr[cg2 + 1]));
        }
    }

    hs[0][tid] = 0.f;
    hs[1][tid] = 0.f;
    if (tid < 64) csm[tid >> 5][tid & 31] = 0.f;
    __syncthreads();

    // preload xg for t=0 (one value per thread, reduce mapping)
    float xv = __ldg(&g_xg[((size_t)((b0 + rb) * TT)) * G4 + rcolg]);

    for (int t = 0; t < TT; t++) {
        // ---- outer-product partial GEMV over this warp's K-slice ----
        const float h0l = hs[0][w * 32 + lane];   // coalesced: 1 float/lane
        const float h1l = hs[1][w * 32 + lane];
        unsigned long long a00 = 0ull, a01 = 0ull, a10 = 0ull, a11 = 0ull;
#pragma unroll
        for (int k = 0; k < 32; k++) {
            const float s0 = __shfl_sync(0xffffffffu, h0l, k);
            const float s1 = __shfl_sync(0xffffffffu, h1l, k);
            const unsigned long long hb0 = pk2(s0, s0);
            const unsigned long long hb1 = pk2(s1, s1);
            a00 = ffma2(w2[k][0], hb0, a00);
            a01 = ffma2(w2[k][1], hb0, a01);
            a10 = ffma2(w2[k][0], hb1, a10);
            a11 = ffma2(w2[k][1], hb1, a11);
        }
        {
            const float2 u0 = unpk2(a00), u1 = unpk2(a01);
            const float2 v0 = unpk2(a10), v1 = unpk2(a11);
            *(float4*)&red[w][0][4 * lane] = make_float4(u0.x, u0.y, u1.x, u1.y);
            *(float4*)&red[w][1][4 * lane] = make_float4(v0.x, v0.y, v1.x, v1.y);
        }
        __syncthreads();   // red ready; also guards hs reads vs later rewrite

        // ---- cross-warp reduce (+xg) -> gate value per (batch, col) ----
        {
            float s = xv;
#pragma unroll
            for (int r = 0; r < 8; r++) s += red[r][rb][rcol];
            gsm[tid] = s;
        }
        __syncthreads();

        const int   sl   = (t + 1) & 1;
        const float tagf = (float)(t + 1);

        // ---- activation (R4 structure): 64 threads = 2 batches x 32 h ----
        if (tid < 64) {
            const int bb = tid >> 5, ll = tid & 31;
            const float* gp = gsm + bb * 128;
            const float gi = gp[ll];
            const float gf = gp[32 + ll];
            const float gg = gp[64 + ll];
            const float go = gp[96 + ll];
            const float cprev = csm[bb][ll];
            const float si = 1.f / (1.f + __expf(-gi));
            const float sf = 1.f / (1.f + __expf(-gf));
            const float so = 1.f / (1.f + __expf(-go));
            const float tg = 2.f / (1.f + __expf(-2.f * gg)) - 1.f;
            const float cn = sf * cprev + si * tg;
            const float tc = 2.f / (1.f + __expf(-2.f * cn)) - 1.f;
            const float hn = so * tc;
            csm[bb][ll] = cn;
            const int bg   = bb ? b1 : b0;
            const int hidx = j * 32 + ll;
            if (t + 1 < TT)
                st_rlx64(&g_hx[sl][grp][hidx][bb], pk2(hn, tagf));
            g_hseq[((size_t)(bg * TT + t)) * HH + hidx] = hn;
        }
        // NO barrier: warps 2-7 go straight to polling while warps 0-1 finish

        if (t + 1 < TT) {
            // prefetch next xg (in flight during the poll)
            xv = __ldg(&g_xg[((size_t)((b0 + rb) * TT + (t + 1))) * G4 + rcolg]);
            // each thread polls its OWN two tagged words; hit == data
            const unsigned long long* src = &g_hx[sl][grp][tid][0];
            float2 d0, d1;
            for (;;) {
                const unsigned long long v0 = ld_rlx64(src);
                const unsigned long long v1 = ld_rlx64(src + 1);
                d0 = unpk2(v0);
                d1 = unpk2(v1);
                if (d0.y >= tagf && d1.y >= tagf) break;
            }
            hs[0][tid] = d0.x;
            hs[1][tid] = d1.x;
            __syncthreads();
        }
    }
}

// ---------------- launch ----------------
extern "C" void kernel_launch(void* const* d_in, const int* in_sizes, int n_in,
                              void* d_out, int out_size)
{
    const float* x  = (const float*)d_in[0];   // [B,T,DIN]
    const float* Wx = (const float*)d_in[1];   // [DIN,4H]
    const float* Wh = (const float*)d_in[2];   // [H,4H]
    const float* b  = (const float*)d_in[3];   // [4H]
    const float* Wo = (const float*)d_in[4];   // [H,DOUT]
    const float* bo = (const float*)d_in[5];   // [DOUT]
    float* out = (float*)d_out;                // [B,T,DOUT]

    float *xg_ptr = nullptr, *hseq_ptr = nullptr;
    cudaGetSymbolAddress((void**)&xg_ptr, g_xg);
    cudaGetSymbolAddress((void**)&hseq_ptr, g_hseq);

    // reset exchange tags (graph replays reuse device state)
    init_kernel<<<64, 256>>>();

    // 1) xg = x @ Wx + b : [131072,256] @ [256,1024]
    {
        dim3 grid(G4 / 128, (BB * TT) / 128);   // (8, 1024)
        sgemm_bias_128<<<grid, 256>>>(x, Wx, b, xg_ptr, BB * TT, G4, DIN);
    }

    // 2) recurrence over 4096 steps (16 groups x 8 CTAs, all co-resident)
    lstm_rec<<<128, 256>>>(Wh);

    // 3) out = hseq @ Wo + bo : [131072,256] @ [256,256]
    {
        dim3 grid(256 / 128, (BB * TT) / 128);  // (2, 1024)
        sgemm_bias_128<<<grid, 256>>>(hseq_ptr, Wo, bo, out, BB * TT, 256, HH);
    }
}